// round 2
// baseline (speedup 1.0000x reference)
#include <cuda_runtime.h>
#include <cuda_fp16.h>
#include <cuda_bf16.h>
#include <math.h>

#define G     128
#define NPG   256
#define DF    128
#define KB    16

// ---- device scratch (no allocations allowed) ----
__device__ float g_sig[2 * G * KB];     // [view][graph][bin]
__device__ float g_rowloss[2 * G];      // per-row ntxent loss

// ---- smem layout for uts_kernel ----
#define HT_STRIDE 257                       // bfloat162 units (pad for conflict-free)
#define OFF_DS   (64 * HT_STRIDE * 4)       // bytes: after Ht[64][257] bf162
#define OFF_SQ   (OFF_DS + NPG * NPG * 2)   // after Ds[256][256] half
#define OFF_RED  (OFF_SQ + NPG * 4)         // after sq[256] float
#define SMEM_A   (OFF_RED + (8 + 8 * KB) * 4)

__device__ __forceinline__ float ex2_approx(float x) {
    float y;
    asm("ex2.approx.ftz.f32 %0, %1;" : "=f"(y) : "f"(x));
    return y;
}

// One CTA per (view, graph). 256 threads.
__global__ void __launch_bounds__(256, 1)
uts_kernel(const float* __restrict__ H1, const float* __restrict__ H2)
{
    const int bx = blockIdx.x;
    const int v  = bx >> 7;
    const int g  = bx & (G - 1);
    const float* __restrict__ H = (v ? H2 : H1) + (size_t)g * NPG * DF;

    extern __shared__ char sraw[];
    __nv_bfloat162* Ht = (__nv_bfloat162*)sraw;          // [64][HT_STRIDE] (k-pair major, transposed)
    half*  Ds  = (half*)(sraw + OFF_DS);                 // [256][256]
    float* sq  = (float*)(sraw + OFF_SQ);                // [256]
    float* red = (float*)(sraw + OFF_RED);               // [8] sums + [8][16] hist

    const int tid = threadIdx.x;
    const int lid = tid & 31;
    const int wid = tid >> 5;

    // ---- load H, convert to bf16, transpose into Ht[kpair][node] ----
    const float2* __restrict__ Hp = (const float2*)H;
    #pragma unroll 8
    for (int it = 0; it < 64; it++) {
        int p  = it * 256 + tid;
        int i  = p >> 6;         // node
        int kk = p & 63;         // k-pair
        float2 f = Hp[i * 64 + kk];
        Ht[kk * HT_STRIDE + i] = __float22bfloat162_rn(f);
    }
    __syncthreads();

    // ---- squared row norms (same summation order as Gram) ----
    {
        float s = 0.f;
        #pragma unroll 8
        for (int kk = 0; kk < 64; kk++) {
            float2 a = __bfloat1622float2(Ht[kk * HT_STRIDE + tid]);
            s = fmaf(a.x, a.x, s);
            s = fmaf(a.y, a.y, s);
        }
        sq[tid] = s;
    }
    __syncthreads();

    // ---- pass 1: Gram -> distances (fp16 in smem), sum of D ----
    const int tx = tid & 15;
    const int ty = tid >> 4;
    float sumD = 0.f;

    for (int bi = 0; bi < 4; bi++) {
        for (int bj = bi; bj < 4; bj++) {
            float acc[4][4];
            #pragma unroll
            for (int r = 0; r < 4; r++)
                #pragma unroll
                for (int c = 0; c < 4; c++) acc[r][c] = 0.f;

            const int i0 = bi * 64 + ty;
            const int j0 = bj * 64 + tx;

            #pragma unroll 4
            for (int kk = 0; kk < 64; kk++) {
                float2 a[4], b[4];
                #pragma unroll
                for (int r = 0; r < 4; r++)
                    a[r] = __bfloat1622float2(Ht[kk * HT_STRIDE + i0 + 16 * r]);
                #pragma unroll
                for (int c = 0; c < 4; c++)
                    b[c] = __bfloat1622float2(Ht[kk * HT_STRIDE + j0 + 16 * c]);
                #pragma unroll
                for (int r = 0; r < 4; r++)
                    #pragma unroll
                    for (int c = 0; c < 4; c++) {
                        acc[r][c] = fmaf(a[r].x, b[c].x, acc[r][c]);
                        acc[r][c] = fmaf(a[r].y, b[c].y, acc[r][c]);
                    }
            }

            #pragma unroll
            for (int r = 0; r < 4; r++) {
                const int i = i0 + 16 * r;
                const float si = sq[i];
                #pragma unroll
                for (int c = 0; c < 4; c++) {
                    const int j = j0 + 16 * c;
                    float d2 = si + sq[j] - 2.f * acc[r][c];
                    float d  = sqrtf(fmaxf(d2, 0.f) + 1e-12f);
                    Ds[i * 256 + j] = __float2half(d);
                    if (bi != bj) {
                        Ds[j * 256 + i] = __float2half(d);
                        sumD += 2.f * d;
                    } else {
                        sumD += d;
                    }
                }
            }
        }
    }

    // reduce sumD across block
    #pragma unroll
    for (int o = 16; o; o >>= 1) sumD += __shfl_xor_sync(0xffffffffu, sumD, o);
    if (lid == 0) red[wid] = sumD;
    __syncthreads();

    float meanD = 0.f;
    #pragma unroll
    for (int w = 0; w < 8; w++) meanD += red[w];
    meanD *= (1.f / 65536.f);

    // xs = D / ((mean+eps)*sigma); sigma = 3/16
    const float inv = 1.f / ((meanD + 1e-8f) * 0.1875f);
    const float RHO = 16.f / 15.f;            // bin spacing / sigma
    const float C2  = -0.72134752044448f;     // -0.5 * log2(e)

    // ---- pass 2: soft histogram ----
    float hist[KB];
    #pragma unroll
    for (int k = 0; k < KB; k++) hist[k] = 0.f;

    #pragma unroll 2
    for (int it = 0; it < 256; it++) {
        float d  = __half2float(Ds[it * 256 + tid]);
        float xs = d * inv;
        #pragma unroll
        for (int k = 0; k < KB; k++) {
            float df = xs - (float)k * RHO;
            hist[k] += ex2_approx(df * df * C2);
        }
    }

    // reduce hist across block
    #pragma unroll
    for (int k = 0; k < KB; k++)
        #pragma unroll
        for (int o = 16; o; o >>= 1)
            hist[k] += __shfl_xor_sync(0xffffffffu, hist[k], o);

    if (lid == 0) {
        #pragma unroll
        for (int k = 0; k < KB; k++) red[8 + wid * KB + k] = hist[k];
    }
    __syncthreads();

    if (tid < KB) {
        float h = 0.f;
        #pragma unroll
        for (int w = 0; w < 8; w++) h += red[8 + w * KB + tid];
        float tot = h;
        #pragma unroll
        for (int o = 8; o; o >>= 1) tot += __shfl_xor_sync(0x0000ffffu, tot, o);
        g_sig[(v * G + g) * KB + tid] = h / (tot + 1e-8f);
    }
}

// ---- NT-Xent rows: 64 CTAs x 4 rows ----
#define Z_STRIDE 129
#define SMEM_B   ((256 * Z_STRIDE + 256 + 16) * 4)

__global__ void __launch_bounds__(256, 1)
ntx_kernel(const float* __restrict__ z1, const float* __restrict__ z2)
{
    extern __shared__ char sraw[];
    float* zs   = (float*)sraw;                 // [256][129]
    float* invn = zs + 256 * Z_STRIDE;          // [256]
    float* red  = invn + 256;                   // [8] + [1] label sim

    const int tid = threadIdx.x;
    const int lid = tid & 31;
    const int wid = tid >> 5;

    // load z1 rows 0..127, z2 rows 128..255 (coalesced)
    for (int idx = tid; idx < 256 * DF; idx += 256) {
        int i = idx >> 7;
        int k = idx & 127;
        float val = (i < G) ? z1[i * DF + k] : z2[(i - G) * DF + k];
        zs[i * Z_STRIDE + k] = val;
    }
    __syncthreads();

    // norms
    {
        float s = 0.f;
        #pragma unroll 8
        for (int k = 0; k < DF; k++) {
            float a = zs[tid * Z_STRIDE + k];
            s = fmaf(a, a, s);
        }
        invn[tid] = 1.f / (sqrtf(s) + 1e-8f);
    }
    __syncthreads();

    const int r0 = blockIdx.x * 4;
    for (int rr = 0; rr < 4; rr++) {
        const int r = r0 + rr;
        float dot = 0.f;
        #pragma unroll 8
        for (int k = 0; k < DF; k++)
            dot = fmaf(zs[r * Z_STRIDE + k], zs[tid * Z_STRIDE + k], dot);

        float sim = dot * invn[r] * invn[tid] * 2.0f;   // 1/TEMP = 2
        if (tid == r) sim = -1e9f;

        const int lbl = (r < G) ? (r + G) : (r - G);
        if (tid == lbl) red[8] = sim;

        float e = expf(sim);
        #pragma unroll
        for (int o = 16; o; o >>= 1) e += __shfl_xor_sync(0xffffffffu, e, o);
        if (lid == 0) red[wid] = e;
        __syncthreads();

        if (tid == 0) {
            float s = 0.f;
            #pragma unroll
            for (int w = 0; w < 8; w++) s += red[w];
            g_rowloss[r] = logf(s) - red[8];
        }
        __syncthreads();
    }
}

// ---- final combine ----
__global__ void __launch_bounds__(256)
final_kernel(float* __restrict__ out)
{
    __shared__ float red[8];
    const int tid = threadIdx.x;

    float a = 0.f;
    // view-0 signatures occupy g_sig[0..2047], view-1 at g_sig[2048..4095]
    #pragma unroll
    for (int idx = tid; idx < G * KB; idx += 256) {
        float d = g_sig[idx] - g_sig[G * KB + idx];   // s1 - s2
        a += d * d;
    }
    a *= (1.f / 2048.f);                 // mean over (graph, bin)
    a += g_rowloss[tid] * (1.f / 256.f); // ntxent mean

    #pragma unroll
    for (int o = 16; o; o >>= 1) a += __shfl_xor_sync(0xffffffffu, a, o);
    if ((tid & 31) == 0) red[tid >> 5] = a;
    __syncthreads();

    if (tid == 0) {
        float t = 0.f;
        #pragma unroll
        for (int w = 0; w < 8; w++) t += red[w];
        out[0] = 0.1f * t;   // LAMBDA
    }
}

extern "C" void kernel_launch(void* const* d_in, const int* in_sizes, int n_in,
                              void* d_out, int out_size)
{
    const float* H1 = (const float*)d_in[0];
    const float* H2 = (const float*)d_in[2];
    const float* z1 = (const float*)d_in[4];
    const float* z2 = (const float*)d_in[5];
    float* out = (float*)d_out;

    cudaFuncSetAttribute(uts_kernel, cudaFuncAttributeMaxDynamicSharedMemorySize, SMEM_A);
    cudaFuncSetAttribute(ntx_kernel, cudaFuncAttributeMaxDynamicSharedMemorySize, SMEM_B);

    uts_kernel<<<256, 256, SMEM_A>>>(H1, H2);
    ntx_kernel<<<64, 256, SMEM_B>>>(z1, z2);
    final_kernel<<<1, 256>>>(out);
}

// round 3
// speedup vs baseline: 2.8873x; 2.8873x over previous
#include <cuda_runtime.h>
#include <cuda_fp16.h>
#include <cuda_bf16.h>
#include <math.h>
#include <stdint.h>

#define G     128
#define NPG   256
#define DF    128
#define KB    16
#define NB    11          // computed bins 0..10 (rest are < e^-12 and written as 0)

// ---- device scratch ----
__device__ float g_sig[2 * G * KB];
__device__ float g_rowloss[2 * G];

// ---- smem layout (bytes) ----
#define HS_STRIDE_B 272                         // 256B row + 16B pad -> conflict-free ldmatrix
#define OFF_DS   (NPG * HS_STRIDE_B)            // 69632
#define DS_STRIDE_H 272                         // halves; 544B rows, 16B aligned
#define OFF_SQ   (OFF_DS + NPG * DS_STRIDE_H * 2)   // 69632+139264 = 208896
#define OFF_ZR   (OFF_SQ + NPG * 4)                 // 209920
#define OFF_RED  (OFF_ZR + DF * 4)                  // 210432
#define SMEM_A   (OFF_RED + 128 * 4)                // 210944 (~206KB)

__device__ __forceinline__ float ex2f(float x) {
    float y; asm("ex2.approx.ftz.f32 %0, %1;" : "=f"(y) : "f"(x)); return y;
}
__device__ __forceinline__ float sqrt_ap(float x) {
    float y; asm("sqrt.approx.ftz.f32 %0, %1;" : "=f"(y) : "f"(x)); return y;
}
__device__ __forceinline__ void ldmx4(uint32_t& r0, uint32_t& r1, uint32_t& r2, uint32_t& r3, uint32_t addr) {
    asm volatile("ldmatrix.sync.aligned.m8n8.x4.shared.b16 {%0,%1,%2,%3}, [%4];"
                 : "=r"(r0), "=r"(r1), "=r"(r2), "=r"(r3) : "r"(addr));
}
__device__ __forceinline__ void mma_bf16(float& c0, float& c1, float& c2, float& c3,
                                         uint32_t a0, uint32_t a1, uint32_t a2, uint32_t a3,
                                         uint32_t b0, uint32_t b1) {
    asm volatile("mma.sync.aligned.m16n8k16.row.col.f32.bf16.bf16.f32 "
                 "{%0,%1,%2,%3}, {%4,%5,%6,%7}, {%8,%9}, {%0,%1,%2,%3};"
                 : "+f"(c0), "+f"(c1), "+f"(c2), "+f"(c3)
                 : "r"(a0), "r"(a1), "r"(a2), "r"(a3), "r"(b0), "r"(b1));
}

// One CTA per (view, graph). 256 threads = 8 warps.
__global__ void __launch_bounds__(256, 1)
uts_kernel(const float* __restrict__ H1, const float* __restrict__ H2,
           const float* __restrict__ z1, const float* __restrict__ z2)
{
    const int bx = blockIdx.x;
    const int v  = bx >> 7;
    const int g  = bx & (G - 1);
    const float* __restrict__ H = (v ? H2 : H1) + (size_t)g * NPG * DF;

    extern __shared__ char sraw[];
    char*  Hs  = sraw;                               // bf16 [256][136 halves] (272B stride)
    half*  Ds  = (half*)(sraw + OFF_DS);             // [256][272 halves]
    float* sq  = (float*)(sraw + OFF_SQ);            // [256] (reused as invn for ntx)
    float* zr  = (float*)(sraw + OFF_ZR);            // [128]
    float* red = (float*)(sraw + OFF_RED);           // scratch reductions

    const int tid  = threadIdx.x;
    const int lane = tid & 31;
    const int wid  = tid >> 5;
    const uint32_t hs_base = (uint32_t)__cvta_generic_to_shared(Hs);

    // ================== load H -> bf16 smem, compute sq from rounded values ==================
    {
        const float4* __restrict__ Hp = (const float4*)H;
        #pragma unroll
        for (int it = 0; it < 16; it++) {
            int id = it * 256 + tid;
            int n  = id >> 4;         // row
            int c  = id & 15;         // 16B chunk within row
            float4 f0 = Hp[n * 32 + 2 * c];
            float4 f1 = Hp[n * 32 + 2 * c + 1];
            __nv_bfloat162 b0 = __float22bfloat162_rn(make_float2(f0.x, f0.y));
            __nv_bfloat162 b1 = __float22bfloat162_rn(make_float2(f0.z, f0.w));
            __nv_bfloat162 b2 = __float22bfloat162_rn(make_float2(f1.x, f1.y));
            __nv_bfloat162 b3 = __float22bfloat162_rn(make_float2(f1.z, f1.w));
            uint4 pk;
            pk.x = *(uint32_t*)&b0; pk.y = *(uint32_t*)&b1;
            pk.z = *(uint32_t*)&b2; pk.w = *(uint32_t*)&b3;
            *(uint4*)(Hs + n * HS_STRIDE_B + c * 16) = pk;
            // square-sum of rounded values (matches HMMA inputs)
            float2 r0 = __bfloat1622float2(b0), r1 = __bfloat1622float2(b1);
            float2 r2 = __bfloat1622float2(b2), r3 = __bfloat1622float2(b3);
            float s = r0.x*r0.x + r0.y*r0.y + r1.x*r1.x + r1.y*r1.y
                    + r2.x*r2.x + r2.y*r2.y + r3.x*r3.x + r3.y*r3.y;
            #pragma unroll
            for (int o = 1; o < 16; o <<= 1) s += __shfl_xor_sync(0xffffffffu, s, o);
            if ((tid & 15) == 0) sq[n] = s;
        }
    }
    __syncthreads();

    // ================== pass 1: tensor-core Gram -> D (fp16 smem), sumD ==================
    float sumD = 0.f;
    {
        const int gq = lane >> 2, tq = lane & 3;       // c-frag coords
        const int j0 = wid * 32;
        const int arow_l = lane & 15, asel = lane >> 4;
        const int brow_l = (lane & 7) + ((lane & 16) >> 1);
        const int bsel   = (lane >> 3) & 1;

        #pragma unroll
        for (int ti = 0; ti < 4; ti++) {
            const int i0 = ti * 64;
            float c[4][4][4];
            #pragma unroll
            for (int ms = 0; ms < 4; ms++)
                #pragma unroll
                for (int ns = 0; ns < 4; ns++)
                    #pragma unroll
                    for (int q = 0; q < 4; q++) c[ms][ns][q] = 0.f;

            #pragma unroll
            for (int s = 0; s < 8; s++) {
                uint32_t A[4][4];
                #pragma unroll
                for (int ms = 0; ms < 4; ms++) {
                    uint32_t addr = hs_base + (uint32_t)((i0 + ms * 16 + arow_l) * HS_STRIDE_B
                                                         + (2 * s + asel) * 16);
                    ldmx4(A[ms][0], A[ms][1], A[ms][2], A[ms][3], addr);
                }
                uint32_t B[2][4];
                #pragma unroll
                for (int nbp = 0; nbp < 2; nbp++) {
                    uint32_t addr = hs_base + (uint32_t)((j0 + nbp * 16 + brow_l) * HS_STRIDE_B
                                                         + (2 * s + bsel) * 16);
                    ldmx4(B[nbp][0], B[nbp][1], B[nbp][2], B[nbp][3], addr);
                }
                #pragma unroll
                for (int ms = 0; ms < 4; ms++)
                    #pragma unroll
                    for (int ns = 0; ns < 4; ns++) {
                        uint32_t b0 = B[ns >> 1][(ns & 1) ? 2 : 0];
                        uint32_t b1 = B[ns >> 1][(ns & 1) ? 3 : 1];
                        mma_bf16(c[ms][ns][0], c[ms][ns][1], c[ms][ns][2], c[ms][ns][3],
                                 A[ms][0], A[ms][1], A[ms][2], A[ms][3], b0, b1);
                    }
            }
            // epilogue: d = sqrt(max(si+sj-2dot,0)+1e-12), store half2, accumulate sumD
            #pragma unroll
            for (int ms = 0; ms < 4; ms++) {
                #pragma unroll
                for (int ns = 0; ns < 4; ns++) {
                    const int i  = i0 + ms * 16 + gq;
                    const int j  = j0 + ns * 8 + 2 * tq;
                    const float sj0 = sq[j], sj1 = sq[j + 1];
                    {
                        float si = sq[i];
                        float d0 = sqrt_ap(fmaxf(si + sj0 - 2.f * c[ms][ns][0], 0.f) + 1e-12f);
                        float d1 = sqrt_ap(fmaxf(si + sj1 - 2.f * c[ms][ns][1], 0.f) + 1e-12f);
                        sumD += d0 + d1;
                        *(__half2*)&Ds[i * DS_STRIDE_H + j] = __floats2half2_rn(d0, d1);
                    }
                    {
                        float si = sq[i + 8];
                        float d0 = sqrt_ap(fmaxf(si + sj0 - 2.f * c[ms][ns][2], 0.f) + 1e-12f);
                        float d1 = sqrt_ap(fmaxf(si + sj1 - 2.f * c[ms][ns][3], 0.f) + 1e-12f);
                        sumD += d0 + d1;
                        *(__half2*)&Ds[(i + 8) * DS_STRIDE_H + j] = __floats2half2_rn(d0, d1);
                    }
                }
            }
        }
    }

    // reduce sumD
    #pragma unroll
    for (int o = 16; o; o >>= 1) sumD += __shfl_xor_sync(0xffffffffu, sumD, o);
    if (lane == 0) red[wid] = sumD;
    __syncthreads();
    float meanD = 0.f;
    #pragma unroll
    for (int w = 0; w < 8; w++) meanD += red[w];
    meanD *= (1.f / 65536.f);

    // ================== pass 2: factorized soft histogram (bins 0..10) ==================
    // w_k = base0(u) * P^k * C_k,  u = xs - 5*RHO, P = e^{u*RHO}
    const float inv = 1.f / ((meanD + 1e-8f) * 0.1875f);
    const float CKS[NB] = {
        6.65834e-7f, 1.11418e-4f, 5.97600e-3f, 1.02737e-1f, 5.66155e-1f,
        1.0f,        5.66155e-1f, 1.02737e-1f, 5.97600e-3f, 1.11418e-4f, 6.65834e-7f };

    float hist[NB];
    #pragma unroll
    for (int k = 0; k < NB; k++) hist[k] = 0.f;

    {
        const uint4* rowp = (const uint4*)((char*)Ds + tid * (DS_STRIDE_H * 2));
        #pragma unroll 4
        for (int q = 0; q < 32; q++) {
            uint4 vv = rowp[q];
            __half2 h[4] = { *(__half2*)&vv.x, *(__half2*)&vv.y, *(__half2*)&vv.z, *(__half2*)&vv.w };
            #pragma unroll
            for (int e = 0; e < 4; e++) {
                float2 dd = __half22float2(h[e]);
                #pragma unroll
                for (int half_i = 0; half_i < 2; half_i++) {
                    float d = half_i ? dd.y : dd.x;
                    float u  = fmaf(d, inv, -5.3333333f);
                    float e0 = u * fmaf(-0.72134752f, u, -7.69437355f);
                    float r  = ex2f(e0);
                    float p  = ex2f(1.53887471f * u);
                    #pragma unroll
                    for (int k = 0; k < NB; k++) {
                        hist[k] = fmaf(r, CKS[k], hist[k]);
                        r *= p;
                    }
                }
            }
        }
    }

    // reduce hist and write signature
    #pragma unroll
    for (int k = 0; k < NB; k++)
        #pragma unroll
        for (int o = 16; o; o >>= 1)
            hist[k] += __shfl_xor_sync(0xffffffffu, hist[k], o);
    if (lane == 0) {
        #pragma unroll
        for (int k = 0; k < NB; k++) red[8 + wid * NB + k] = hist[k];
    }
    __syncthreads();

    if (tid < KB) {
        float h = 0.f;
        if (tid < NB) {
            #pragma unroll
            for (int w = 0; w < 8; w++) h += red[8 + w * NB + tid];
        }
        float tot = h;
        #pragma unroll
        for (int o = 8; o; o >>= 1) tot += __shfl_xor_sync(0x0000ffffu, tot, o);
        g_sig[bx * KB + tid] = h / (tot + 1e-8f);
    }
    __syncthreads();

    // ================== NT-Xent row bx (folded in; L2-resident z) ==================
    {
        float* invn = sq;   // reuse
        const float* zp = (tid < G) ? (z1 + tid * DF) : (z2 + (tid - G) * DF);
        const float4* zp4 = (const float4*)zp;
        float s = 0.f;
        #pragma unroll 8
        for (int k = 0; k < 32; k++) {
            float4 a = zp4[k];
            s = fmaf(a.x, a.x, fmaf(a.y, a.y, fmaf(a.z, a.z, fmaf(a.w, a.w, s))));
        }
        invn[tid] = 1.f / (sqrtf(s) + 1e-8f);

        const float* zrp = (bx < G) ? (z1 + bx * DF) : (z2 + (bx - G) * DF);
        if (tid < 32) ((float4*)zr)[tid] = ((const float4*)zrp)[tid];
        __syncthreads();

        float dot = 0.f;
        const float4* zr4 = (const float4*)zr;
        #pragma unroll 8
        for (int k = 0; k < 32; k++) {
            float4 a = zp4[k], b = zr4[k];
            dot = fmaf(a.x, b.x, fmaf(a.y, b.y, fmaf(a.z, b.z, fmaf(a.w, b.w, dot))));
        }
        float sim = dot * invn[bx] * invn[tid] * 2.0f;   // 1/TEMP
        const int lbl = bx ^ G;
        if (tid == lbl) red[120] = sim;

        float e = (tid == bx) ? 0.f : expf(sim);
        #pragma unroll
        for (int o = 16; o; o >>= 1) e += __shfl_xor_sync(0xffffffffu, e, o);
        __syncthreads();          // protect red[0..7] reuse
        if (lane == 0) red[wid] = e;
        __syncthreads();
        if (tid == 0) {
            float S = 0.f;
            #pragma unroll
            for (int w = 0; w < 8; w++) S += red[w];
            g_rowloss[bx] = logf(S) - red[120];
        }
    }
}

// ---- final combine ----
__global__ void __launch_bounds__(256)
final_kernel(float* __restrict__ out)
{
    __shared__ float red[8];
    const int tid = threadIdx.x;

    float a = 0.f;
    #pragma unroll
    for (int idx = tid; idx < G * KB; idx += 256) {
        float d = g_sig[idx] - g_sig[G * KB + idx];
        a += d * d;
    }
    a *= (1.f / 2048.f);
    a += g_rowloss[tid] * (1.f / 256.f);

    #pragma unroll
    for (int o = 16; o; o >>= 1) a += __shfl_xor_sync(0xffffffffu, a, o);
    if ((tid & 31) == 0) red[tid >> 5] = a;
    __syncthreads();

    if (tid == 0) {
        float t = 0.f;
        #pragma unroll
        for (int w = 0; w < 8; w++) t += red[w];
        out[0] = 0.1f * t;
    }
}

extern "C" void kernel_launch(void* const* d_in, const int* in_sizes, int n_in,
                              void* d_out, int out_size)
{
    const float* H1 = (const float*)d_in[0];
    const float* H2 = (const float*)d_in[2];
    const float* z1 = (const float*)d_in[4];
    const float* z2 = (const float*)d_in[5];
    float* out = (float*)d_out;

    cudaFuncSetAttribute(uts_kernel, cudaFuncAttributeMaxDynamicSharedMemorySize, SMEM_A);

    uts_kernel<<<256, 256, SMEM_A>>>(H1, H2, z1, z2);
    final_kernel<<<1, 256>>>(out);
}

// round 4
// speedup vs baseline: 3.0686x; 1.0628x over previous
#include <cuda_runtime.h>
#include <cuda_fp16.h>
#include <cuda_bf16.h>
#include <math.h>
#include <stdint.h>

#define G     128
#define NPG   256
#define DF    128
#define KB    16
#define NB    11          // computed bins 0..10 (rest < e^-12, left zero)

// ---- device scratch ----
__device__ float    g_sig[2 * G * KB];
__device__ float    g_rowloss[2 * G];
__device__ __half   g_Ds[256 * NPG * NPG];   // 33.5MB distance scratch (upper tri valid)
__device__ unsigned g_ctr = 0;

// ---- smem layout (bytes) ----
#define HS_STRIDE_B 272                      // 256B row + 16B pad -> conflict-free ldmatrix
#define OFF_SQ   (NPG * HS_STRIDE_B)         // 69632
#define OFF_ZR   (OFF_SQ + NPG * 4)          // 70656
#define OFF_RED  (OFF_ZR + DF * 4)           // 71168
#define SMEM_A   (OFF_RED + 128 * 4)         // 71680 (~70KB) -> 2 CTAs/SM

__device__ __forceinline__ float ex2f(float x) {
    float y; asm("ex2.approx.ftz.f32 %0, %1;" : "=f"(y) : "f"(x)); return y;
}
__device__ __forceinline__ float sqrt_ap(float x) {
    float y; asm("sqrt.approx.ftz.f32 %0, %1;" : "=f"(y) : "f"(x)); return y;
}
__device__ __forceinline__ void ldmx4(uint32_t& r0, uint32_t& r1, uint32_t& r2, uint32_t& r3, uint32_t addr) {
    asm volatile("ldmatrix.sync.aligned.m8n8.x4.shared.b16 {%0,%1,%2,%3}, [%4];"
                 : "=r"(r0), "=r"(r1), "=r"(r2), "=r"(r3) : "r"(addr));
}
__device__ __forceinline__ void mma_bf16(float& c0, float& c1, float& c2, float& c3,
                                         uint32_t a0, uint32_t a1, uint32_t a2, uint32_t a3,
                                         uint32_t b0, uint32_t b1) {
    asm volatile("mma.sync.aligned.m16n8k16.row.col.f32.bf16.bf16.f32 "
                 "{%0,%1,%2,%3}, {%4,%5,%6,%7}, {%8,%9}, {%0,%1,%2,%3};"
                 : "+f"(c0), "+f"(c1), "+f"(c2), "+f"(c3)
                 : "r"(a0), "r"(a1), "r"(a2), "r"(a3), "r"(b0), "r"(b1));
}

// One CTA per (view, graph). 256 threads = 8 warps. 2 CTAs/SM.
__global__ void __launch_bounds__(256, 2)
uts_kernel(const float* __restrict__ H1, const float* __restrict__ H2,
           const float* __restrict__ z1, const float* __restrict__ z2,
           float* __restrict__ out)
{
    const int bx = blockIdx.x;
    const int v  = bx >> 7;
    const int g  = bx & (G - 1);
    const float* __restrict__ H = (v ? H2 : H1) + (size_t)g * NPG * DF;
    __half* __restrict__ Dg = g_Ds + (size_t)bx * (NPG * NPG);

    extern __shared__ char sraw[];
    char*  Hs  = sraw;                               // bf16 [256][136 halves]
    float* sq  = (float*)(sraw + OFF_SQ);            // [256] (reused as invn)
    float* zr  = (float*)(sraw + OFF_ZR);            // [128]
    float* red = (float*)(sraw + OFF_RED);           // [128] scratch

    const int tid  = threadIdx.x;
    const int lane = tid & 31;
    const int wid  = tid >> 5;
    const uint32_t hs_base = (uint32_t)__cvta_generic_to_shared(Hs);

    // ================== load H -> bf16 smem + sq (from rounded values) ==================
    {
        const float4* __restrict__ Hp = (const float4*)H;
        #pragma unroll
        for (int it = 0; it < 16; it++) {
            int id = it * 256 + tid;
            int n  = id >> 4;
            int c  = id & 15;
            float4 f0 = Hp[n * 32 + 2 * c];
            float4 f1 = Hp[n * 32 + 2 * c + 1];
            __nv_bfloat162 b0 = __float22bfloat162_rn(make_float2(f0.x, f0.y));
            __nv_bfloat162 b1 = __float22bfloat162_rn(make_float2(f0.z, f0.w));
            __nv_bfloat162 b2 = __float22bfloat162_rn(make_float2(f1.x, f1.y));
            __nv_bfloat162 b3 = __float22bfloat162_rn(make_float2(f1.z, f1.w));
            uint4 pk;
            pk.x = *(uint32_t*)&b0; pk.y = *(uint32_t*)&b1;
            pk.z = *(uint32_t*)&b2; pk.w = *(uint32_t*)&b3;
            *(uint4*)(Hs + n * HS_STRIDE_B + c * 16) = pk;
            float2 r0 = __bfloat1622float2(b0), r1 = __bfloat1622float2(b1);
            float2 r2 = __bfloat1622float2(b2), r3 = __bfloat1622float2(b3);
            float s = r0.x*r0.x + r0.y*r0.y + r1.x*r1.x + r1.y*r1.y
                    + r2.x*r2.x + r2.y*r2.y + r3.x*r3.x + r3.y*r3.y;
            #pragma unroll
            for (int o = 1; o < 16; o <<= 1) s += __shfl_xor_sync(0xffffffffu, s, o);
            if ((tid & 15) == 0) sq[n] = s;
        }
    }
    __syncthreads();

    // ================== pass 1: block-upper-triangle Gram -> d (global fp16), sumD ==================
    // warp -> col-block b so that SMSP pairs (w, w+4) get blocks (b, 7-b): equal work per SMSP
    float sumD = 0.f;
    {
        const int b  = (wid < 4) ? wid : 11 - wid;   // col block 0..7
        const int j0 = b * 32;
        const int gq = lane >> 2, tq = lane & 3;
        const int arow_l = lane & 15, asel = lane >> 4;
        const int brow_l = (lane & 7) + ((lane & 16) >> 1);
        const int bsel   = (lane >> 3) & 1;

        for (int rt = 0; rt <= b; rt++) {            // 32-row tiles, only rt<=b needed
            const int i0 = rt * 32;
            float c[2][4][4];
            #pragma unroll
            for (int ms = 0; ms < 2; ms++)
                #pragma unroll
                for (int ns = 0; ns < 4; ns++)
                    #pragma unroll
                    for (int q = 0; q < 4; q++) c[ms][ns][q] = 0.f;

            #pragma unroll
            for (int s = 0; s < 8; s++) {
                uint32_t A[2][4];
                #pragma unroll
                for (int ms = 0; ms < 2; ms++) {
                    uint32_t addr = hs_base + (uint32_t)((i0 + ms * 16 + arow_l) * HS_STRIDE_B
                                                         + (2 * s + asel) * 16);
                    ldmx4(A[ms][0], A[ms][1], A[ms][2], A[ms][3], addr);
                }
                uint32_t B[2][4];
                #pragma unroll
                for (int nbp = 0; nbp < 2; nbp++) {
                    uint32_t addr = hs_base + (uint32_t)((j0 + nbp * 16 + brow_l) * HS_STRIDE_B
                                                         + (2 * s + bsel) * 16);
                    ldmx4(B[nbp][0], B[nbp][1], B[nbp][2], B[nbp][3], addr);
                }
                #pragma unroll
                for (int ms = 0; ms < 2; ms++)
                    #pragma unroll
                    for (int ns = 0; ns < 4; ns++) {
                        uint32_t bb0 = B[ns >> 1][(ns & 1) ? 2 : 0];
                        uint32_t bb1 = B[ns >> 1][(ns & 1) ? 3 : 1];
                        mma_bf16(c[ms][ns][0], c[ms][ns][1], c[ms][ns][2], c[ms][ns][3],
                                 A[ms][0], A[ms][1], A[ms][2], A[ms][3], bb0, bb1);
                    }
            }

            if (rt < b) {
                // fully strictly-upper tile: weight 2, vector store
                #pragma unroll
                for (int ms = 0; ms < 2; ms++) {
                    #pragma unroll
                    for (int ns = 0; ns < 4; ns++) {
                        const int i  = i0 + ms * 16 + gq;
                        const int j  = j0 + ns * 8 + 2 * tq;
                        const float sj0 = sq[j], sj1 = sq[j + 1];
                        float si = sq[i];
                        float d0 = sqrt_ap(fmaxf(si + sj0 - 2.f * c[ms][ns][0], 0.f) + 1e-12f);
                        float d1 = sqrt_ap(fmaxf(si + sj1 - 2.f * c[ms][ns][1], 0.f) + 1e-12f);
                        *(__half2*)&Dg[i * 256 + j] = __floats2half2_rn(d0, d1);
                        float si8 = sq[i + 8];
                        float d2 = sqrt_ap(fmaxf(si8 + sj0 - 2.f * c[ms][ns][2], 0.f) + 1e-12f);
                        float d3 = sqrt_ap(fmaxf(si8 + sj1 - 2.f * c[ms][ns][3], 0.f) + 1e-12f);
                        *(__half2*)&Dg[(i + 8) * 256 + j] = __floats2half2_rn(d2, d3);
                        sumD += 2.f * (d0 + d1 + d2 + d3);
                    }
                }
            } else {
                // diagonal tile: per-element triangle logic
                #pragma unroll
                for (int ms = 0; ms < 2; ms++) {
                    #pragma unroll
                    for (int ns = 0; ns < 4; ns++) {
                        const int jj = j0 + ns * 8 + 2 * tq;
                        const float sj0 = sq[jj], sj1 = sq[jj + 1];
                        #pragma unroll
                        for (int h = 0; h < 2; h++) {
                            const int i = i0 + ms * 16 + gq + 8 * h;
                            const float si = sq[i];
                            const float cv0 = c[ms][ns][2 * h], cv1 = c[ms][ns][2 * h + 1];
                            if (jj >= i) {
                                float d0 = sqrt_ap(fmaxf(si + sj0 - 2.f * cv0, 0.f) + 1e-12f);
                                Dg[i * 256 + jj] = __float2half(d0);
                                sumD += (jj > i) ? 2.f * d0 : d0;
                            }
                            if (jj + 1 >= i) {
                                float d1 = sqrt_ap(fmaxf(si + sj1 - 2.f * cv1, 0.f) + 1e-12f);
                                Dg[i * 256 + jj + 1] = __float2half(d1);
                                sumD += (jj + 1 > i) ? 2.f * d1 : d1;
                            }
                        }
                    }
                }
            }
        }
    }

    // reduce sumD
    #pragma unroll
    for (int o = 16; o; o >>= 1) sumD += __shfl_xor_sync(0xffffffffu, sumD, o);
    if (lane == 0) red[wid] = sumD;
    __syncthreads();   // also makes Dg writes visible CTA-wide
    float meanD = 0.f;
    #pragma unroll
    for (int w = 0; w < 8; w++) meanD += red[w];
    meanD *= (1.f / 65536.f);

    // ================== pass 2: upper-tri factorized histogram ==================
    const float inv = 1.f / ((meanD + 1e-8f) * 0.1875f);
    const float CKS[NB] = {
        6.65834e-7f, 1.11418e-4f, 5.97600e-3f, 1.02737e-1f, 5.66155e-1f,
        1.0f,        5.66155e-1f, 1.02737e-1f, 5.97600e-3f, 1.11418e-4f, 6.65834e-7f };

    float hist[NB];
    {
        // row assignment: warp w heavy rows pair with warp w+4 light rows on same SMSP
        const int r = (tid < 128) ? tid : 383 - tid;
        const __half* rowp = Dg + r * 256;

        // diagonal element, weight 1 (initializes hist)
        {
            float d  = __half2float(rowp[r]);
            float u  = fmaf(d, inv, -5.3333333f);
            float e0 = u * fmaf(-0.72134752f, u, -7.69437355f);
            float rr = ex2f(e0);
            float p  = ex2f(1.53887471f * u);
            #pragma unroll
            for (int k = 0; k < NB; k++) { hist[k] = rr * CKS[k]; rr *= p; }
        }
        // strictly-upper elements, weight 2 folded into exponent (+1 in log2)
        #pragma unroll 4
        for (int j = r + 1; j < 256; j++) {
            float d  = __half2float(rowp[j]);
            float u  = fmaf(d, inv, -5.3333333f);
            float e0 = fmaf(u, fmaf(-0.72134752f, u, -7.69437355f), 1.0f);
            float rr = ex2f(e0);
            float p  = ex2f(1.53887471f * u);
            #pragma unroll
            for (int k = 0; k < NB; k++) { hist[k] = fmaf(rr, CKS[k], hist[k]); rr *= p; }
        }
    }

    // reduce hist, write signature
    #pragma unroll
    for (int k = 0; k < NB; k++)
        #pragma unroll
        for (int o = 16; o; o >>= 1)
            hist[k] += __shfl_xor_sync(0xffffffffu, hist[k], o);
    if (lane == 0) {
        #pragma unroll
        for (int k = 0; k < NB; k++) red[8 + wid * NB + k] = hist[k];
    }
    __syncthreads();

    if (tid < KB) {
        float h = 0.f;
        if (tid < NB) {
            #pragma unroll
            for (int w = 0; w < 8; w++) h += red[8 + w * NB + tid];
        }
        float tot = h;
        #pragma unroll
        for (int o = 8; o; o >>= 1) tot += __shfl_xor_sync(0x0000ffffu, tot, o);
        g_sig[bx * KB + tid] = h / (tot + 1e-8f);
    }
    __syncthreads();

    // ================== NT-Xent row bx ==================
    {
        float* invn = sq;   // reuse
        const float* zp = (tid < G) ? (z1 + tid * DF) : (z2 + (tid - G) * DF);
        const float4* zp4 = (const float4*)zp;
        float s = 0.f;
        #pragma unroll 8
        for (int k = 0; k < 32; k++) {
            float4 a = zp4[k];
            s = fmaf(a.x, a.x, fmaf(a.y, a.y, fmaf(a.z, a.z, fmaf(a.w, a.w, s))));
        }
        invn[tid] = 1.f / (sqrtf(s) + 1e-8f);

        const float* zrp = (bx < G) ? (z1 + bx * DF) : (z2 + (bx - G) * DF);
        if (tid < 32) ((float4*)zr)[tid] = ((const float4*)zrp)[tid];
        __syncthreads();

        float dot = 0.f;
        const float4* zr4 = (const float4*)zr;
        #pragma unroll 8
        for (int k = 0; k < 32; k++) {
            float4 a = zp4[k], b2 = zr4[k];
            dot = fmaf(a.x, b2.x, fmaf(a.y, b2.y, fmaf(a.z, b2.z, fmaf(a.w, b2.w, dot))));
        }
        float sim = dot * invn[bx] * invn[tid] * 2.0f;   // 1/TEMP
        const int lbl = bx ^ G;
        if (tid == lbl) red[120] = sim;

        float e = (tid == bx) ? 0.f : expf(sim);
        #pragma unroll
        for (int o = 16; o; o >>= 1) e += __shfl_xor_sync(0xffffffffu, e, o);
        __syncthreads();
        if (lane == 0) red[wid] = e;
        __syncthreads();
        if (tid == 0) {
            float S = 0.f;
            #pragma unroll
            for (int w = 0; w < 8; w++) S += red[w];
            g_rowloss[bx] = logf(S) - red[120];
        }
    }

    // ================== last CTA does the final reduction ==================
    __shared__ unsigned amLast;
    __syncthreads();
    if (tid == 0) {
        __threadfence();
        unsigned vv = atomicInc(&g_ctr, 255);   // wraps to 0 at 255: self-reset per launch
        amLast = (vv == 255) ? 1u : 0u;
    }
    __syncthreads();

    if (amLast) {
        __threadfence();
        float a = 0.f;
        for (int idx = tid; idx < G * KB; idx += 256) {
            float d = g_sig[idx] - g_sig[G * KB + idx];
            a += d * d;
        }
        a *= (1.f / 2048.f);
        a += g_rowloss[tid] * (1.f / 256.f);
        #pragma unroll
        for (int o = 16; o; o >>= 1) a += __shfl_xor_sync(0xffffffffu, a, o);
        if (lane == 0) red[64 + wid] = a;
        __syncthreads();
        if (tid == 0) {
            float t = 0.f;
            #pragma unroll
            for (int w = 0; w < 8; w++) t += red[64 + w];
            out[0] = 0.1f * t;
        }
    }
}

extern "C" void kernel_launch(void* const* d_in, const int* in_sizes, int n_in,
                              void* d_out, int out_size)
{
    const float* H1 = (const float*)d_in[0];
    const float* H2 = (const float*)d_in[2];
    const float* z1 = (const float*)d_in[4];
    const float* z2 = (const float*)d_in[5];
    float* out = (float*)d_out;

    cudaFuncSetAttribute(uts_kernel, cudaFuncAttributeMaxDynamicSharedMemorySize, SMEM_A);
    uts_kernel<<<256, 256, SMEM_A>>>(H1, H2, z1, z2, out);
}

// round 7
// speedup vs baseline: 3.5133x; 1.1449x over previous
#include <cuda_runtime.h>
#include <cuda_fp16.h>
#include <cuda_bf16.h>
#include <math.h>
#include <stdint.h>

#define G     128
#define NPG   256
#define DF    128
#define KB    16
#define NB    11          // bins 0..10 (rest < e^-12, left zero)
#define NCHUNK 4224       // 16B chunks covering upper triangle (incl. alignment slack)

// ---- device scratch ----
__device__ float    g_sig[2 * G * KB];
__device__ float    g_rowloss[2 * G];
__device__ __half   g_Ds[256 * NPG * NPG];   // 33.5MB distance scratch
__device__ unsigned g_ctr = 0;

// ---- smem layout (bytes) ----
#define HS_STRIDE_B 272
#define OFF_SQ   (NPG * HS_STRIDE_B)
#define OFF_ZR   (OFF_SQ + NPG * 4)
#define OFF_RED  (OFF_ZR + DF * 4)
#define SMEM_A   (OFF_RED + 128 * 4)         // ~70KB -> 2 CTAs/SM

__device__ __forceinline__ float sqrt_ap(float x) {
    float y; asm("sqrt.approx.ftz.f32 %0, %1;" : "=f"(y) : "f"(x)); return y;
}
__device__ __forceinline__ __half2 h2ex2(__half2 x) {
    uint32_t xi = *(uint32_t*)&x, yi;
    asm("ex2.approx.f16x2 %0, %1;" : "=r"(yi) : "r"(xi));
    return *(__half2*)&yi;
}
__device__ __forceinline__ void ldmx4(uint32_t& r0, uint32_t& r1, uint32_t& r2, uint32_t& r3, uint32_t addr) {
    asm volatile("ldmatrix.sync.aligned.m8n8.x4.shared.b16 {%0,%1,%2,%3}, [%4];"
                 : "=r"(r0), "=r"(r1), "=r"(r2), "=r"(r3) : "r"(addr));
}
__device__ __forceinline__ void mma_bf16(float& c0, float& c1, float& c2, float& c3,
                                         uint32_t a0, uint32_t a1, uint32_t a2, uint32_t a3,
                                         uint32_t b0, uint32_t b1) {
    asm volatile("mma.sync.aligned.m16n8k16.row.col.f32.bf16.bf16.f32 "
                 "{%0,%1,%2,%3}, {%4,%5,%6,%7}, {%8,%9}, {%0,%1,%2,%3};"
                 : "+f"(c0), "+f"(c1), "+f"(c2), "+f"(c3)
                 : "r"(a0), "r"(a1), "r"(a2), "r"(a3), "r"(b0), "r"(b1));
}

// One CTA per (view, graph). 256 threads = 8 warps. 2 CTAs/SM.
__global__ void __launch_bounds__(256, 2)
uts_kernel(const float* __restrict__ H1, const float* __restrict__ H2,
           const float* __restrict__ z1, const float* __restrict__ z2,
           float* __restrict__ out)
{
    const int bx = blockIdx.x;
    const int v  = bx >> 7;
    const int g  = bx & (G - 1);
    const float* __restrict__ H = (v ? H2 : H1) + (size_t)g * NPG * DF;
    __half* __restrict__ Dg = g_Ds + (size_t)bx * (NPG * NPG);

    extern __shared__ char sraw[];
    char*  Hs  = sraw;
    float* sq  = (float*)(sraw + OFF_SQ);
    float* zr  = (float*)(sraw + OFF_ZR);
    float* red = (float*)(sraw + OFF_RED);

    const int tid  = threadIdx.x;
    const int lane = tid & 31;
    const int wid  = tid >> 5;
    const uint32_t hs_base = (uint32_t)__cvta_generic_to_shared(Hs);

    // ================== load H -> bf16 smem + sq ==================
    {
        const float4* __restrict__ Hp = (const float4*)H;
        #pragma unroll
        for (int it = 0; it < 16; it++) {
            int id = it * 256 + tid;
            int n  = id >> 4;
            int c  = id & 15;
            float4 f0 = Hp[n * 32 + 2 * c];
            float4 f1 = Hp[n * 32 + 2 * c + 1];
            __nv_bfloat162 b0 = __float22bfloat162_rn(make_float2(f0.x, f0.y));
            __nv_bfloat162 b1 = __float22bfloat162_rn(make_float2(f0.z, f0.w));
            __nv_bfloat162 b2 = __float22bfloat162_rn(make_float2(f1.x, f1.y));
            __nv_bfloat162 b3 = __float22bfloat162_rn(make_float2(f1.z, f1.w));
            uint4 pk;
            pk.x = *(uint32_t*)&b0; pk.y = *(uint32_t*)&b1;
            pk.z = *(uint32_t*)&b2; pk.w = *(uint32_t*)&b3;
            *(uint4*)(Hs + n * HS_STRIDE_B + c * 16) = pk;
            float2 r0 = __bfloat1622float2(b0), r1 = __bfloat1622float2(b1);
            float2 r2 = __bfloat1622float2(b2), r3 = __bfloat1622float2(b3);
            float s = r0.x*r0.x + r0.y*r0.y + r1.x*r1.x + r1.y*r1.y
                    + r2.x*r2.x + r2.y*r2.y + r3.x*r3.x + r3.y*r3.y;
            #pragma unroll
            for (int o = 1; o < 16; o <<= 1) s += __shfl_xor_sync(0xffffffffu, s, o);
            if ((tid & 15) == 0) sq[n] = s;
        }
    }
    __syncthreads();

    // ================== pass 1: upper-tri Gram -> d (fp16 global), sumD ==================
    float sumD = 0.f;
    {
        const int b  = (wid < 4) ? wid : 11 - wid;   // col block; SMSP-balanced
        const int j0 = b * 32;
        const int gq = lane >> 2, tq = lane & 3;
        const int arow_l = lane & 15, asel = lane >> 4;
        const int brow_l = (lane & 7) + ((lane & 16) >> 1);
        const int bsel   = (lane >> 3) & 1;

        for (int rt = 0; rt <= b; rt++) {
            const int i0 = rt * 32;
            float c[2][4][4];
            #pragma unroll
            for (int ms = 0; ms < 2; ms++)
                #pragma unroll
                for (int ns = 0; ns < 4; ns++)
                    #pragma unroll
                    for (int q = 0; q < 4; q++) c[ms][ns][q] = 0.f;

            #pragma unroll
            for (int s = 0; s < 8; s++) {
                uint32_t A[2][4];
                #pragma unroll
                for (int ms = 0; ms < 2; ms++) {
                    uint32_t addr = hs_base + (uint32_t)((i0 + ms * 16 + arow_l) * HS_STRIDE_B
                                                         + (2 * s + asel) * 16);
                    ldmx4(A[ms][0], A[ms][1], A[ms][2], A[ms][3], addr);
                }
                uint32_t B[2][4];
                #pragma unroll
                for (int nbp = 0; nbp < 2; nbp++) {
                    uint32_t addr = hs_base + (uint32_t)((j0 + nbp * 16 + brow_l) * HS_STRIDE_B
                                                         + (2 * s + bsel) * 16);
                    ldmx4(B[nbp][0], B[nbp][1], B[nbp][2], B[nbp][3], addr);
                }
                #pragma unroll
                for (int ms = 0; ms < 2; ms++)
                    #pragma unroll
                    for (int ns = 0; ns < 4; ns++) {
                        uint32_t bb0 = B[ns >> 1][(ns & 1) ? 2 : 0];
                        uint32_t bb1 = B[ns >> 1][(ns & 1) ? 3 : 1];
                        mma_bf16(c[ms][ns][0], c[ms][ns][1], c[ms][ns][2], c[ms][ns][3],
                                 A[ms][0], A[ms][1], A[ms][2], A[ms][3], bb0, bb1);
                    }
            }

            if (rt < b) {
                #pragma unroll
                for (int ms = 0; ms < 2; ms++) {
                    #pragma unroll
                    for (int ns = 0; ns < 4; ns++) {
                        const int i  = i0 + ms * 16 + gq;
                        const int j  = j0 + ns * 8 + 2 * tq;
                        const float sj0 = sq[j], sj1 = sq[j + 1];
                        float si = sq[i];
                        float d0 = sqrt_ap(fmaxf(si + sj0 - 2.f * c[ms][ns][0], 0.f) + 1e-12f);
                        float d1 = sqrt_ap(fmaxf(si + sj1 - 2.f * c[ms][ns][1], 0.f) + 1e-12f);
                        *(__half2*)&Dg[i * 256 + j] = __floats2half2_rn(d0, d1);
                        float si8 = sq[i + 8];
                        float d2 = sqrt_ap(fmaxf(si8 + sj0 - 2.f * c[ms][ns][2], 0.f) + 1e-12f);
                        float d3 = sqrt_ap(fmaxf(si8 + sj1 - 2.f * c[ms][ns][3], 0.f) + 1e-12f);
                        *(__half2*)&Dg[(i + 8) * 256 + j] = __floats2half2_rn(d2, d3);
                        sumD += 2.f * (d0 + d1 + d2 + d3);
                    }
                }
            } else {
                // diagonal tile: write jj >= i-7 (alignment slack for pass 2), weight only jj>=i
                #pragma unroll
                for (int ms = 0; ms < 2; ms++) {
                    #pragma unroll
                    for (int ns = 0; ns < 4; ns++) {
                        const int jj = j0 + ns * 8 + 2 * tq;
                        const float sj0 = sq[jj], sj1 = sq[jj + 1];
                        #pragma unroll
                        for (int h = 0; h < 2; h++) {
                            const int i = i0 + ms * 16 + gq + 8 * h;
                            const float si = sq[i];
                            const float cv0 = c[ms][ns][2 * h], cv1 = c[ms][ns][2 * h + 1];
                            if (jj >= i - 7) {
                                float d0 = sqrt_ap(fmaxf(si + sj0 - 2.f * cv0, 0.f) + 1e-12f);
                                Dg[i * 256 + jj] = __float2half(d0);
                                if (jj >= i) sumD += (jj > i) ? 2.f * d0 : d0;
                            }
                            if (jj + 1 >= i - 7) {
                                float d1 = sqrt_ap(fmaxf(si + sj1 - 2.f * cv1, 0.f) + 1e-12f);
                                Dg[i * 256 + jj + 1] = __float2half(d1);
                                if (jj + 1 >= i) sumD += (jj + 1 > i) ? 2.f * d1 : d1;
                            }
                        }
                    }
                }
            }
        }
    }

    // reduce sumD
    #pragma unroll
    for (int o = 16; o; o >>= 1) sumD += __shfl_xor_sync(0xffffffffu, sumD, o);
    if (lane == 0) red[wid] = sumD;
    __syncthreads();
    float meanD = 0.f;
    #pragma unroll
    for (int w = 0; w < 8; w++) meanD += red[w];
    meanD *= (1.f / 65536.f);

    // ================== pass 2: coalesced chunks, packed fp16 center-out chain ==================
    const float invf = 1.f / ((meanD + 1e-8f) * 0.1875f);
    const __half2 inv2  = __float2half2_rn(invf);
    const __half2 off2  = __float2half2_rn(-5.3333333f);
    const __half2 A2    = __float2half2_rn(-0.72134752f);
    const __half2 RHO2  = __float2half2_rn(1.53887471f);
    const __half2 ONE2  = __float2half2_rn(1.0f);
    const __half2 UMAX2 = __float2half2_rn(5.4f);
    const __half2 UMIN2 = __float2half2_rn(-5.4f);
    // step ratio m=1..5: 2^{-0.820734*(2m-1)}  (cumulative product reproduces CKS exactly)
    const __half2 RS2[5] = { __float2half2_rn(0.566155f),  __float2half2_rn(0.181456f),
                             __float2half2_rn(0.0581705f), __float2half2_rn(0.0186443f),
                             __float2half2_rn(0.00597603f) };

    float histf[NB];
    #pragma unroll
    for (int k = 0; k < NB; k++) histf[k] = 0.f;

    const char* Dgb = (const char*)Dg;
    for (int it = 0; it < 17; it++) {
        int w = it * 256 + tid;
        if (w >= NCHUNK) break;
        // decode chunk -> (row r, chunk col c); f(q) = 260q - 4q^2
        int q = (int)((65.f - sqrtf(4225.f - (float)w)) * 0.5f);
        if (260 * (q + 1) - 4 * (q + 1) * (q + 1) <= w) q++;
        if (260 * q - 4 * q * q > w) q--;
        int rem = w - (260 * q - 4 * q * q);
        int cnt = 32 - q;
        int ro  = rem / cnt;
        int r   = q * 8 + ro;
        int c   = q + (rem - ro * cnt);

        uint4 vv = *(const uint4*)(Dgb + r * 512 + c * 16);
        __half2 dd[4] = { *(__half2*)&vv.x, *(__half2*)&vv.y, *(__half2*)&vv.z, *(__half2*)&vv.w };

        __half2 wl[4];
        if (c == q) {               // chunk contains/abuts the diagonal: per-element log2-weights
            int jb = c * 8;
            #pragma unroll
            for (int e = 0; e < 4; e++) {
                int jl = jb + 2 * e;
                float wlo = (jl     > r) ? 1.f : ((jl     == r) ? 0.f : -300.f);
                float whi = (jl + 1 > r) ? 1.f : ((jl + 1 == r) ? 0.f : -300.f);
                wl[e] = __floats2half2_rn(wlo, whi);
            }
        } else {
            #pragma unroll
            for (int e = 0; e < 4; e++) wl[e] = ONE2;   // strictly upper: weight 2 (log2 = 1)
        }

        __half2 h2a[NB];
        #pragma unroll
        for (int k = 0; k < NB; k++) h2a[k] = __float2half2_rn(0.f);

        #pragma unroll
        for (int e = 0; e < 4; e++) {
            __half2 u2 = __hfma2(dd[e], inv2, off2);
            u2 = __hmax2(__hmin2(u2, UMAX2), UMIN2);    // |pu| <= 8.31 -> P,Pi <= 317, no inf
            __half2 us = __hmul2(u2, u2);
            __half2 e0 = __hfma2(us, A2, wl[e]);
            __half2 w5 = h2ex2(e0);                     // <= 2
            __half2 pu = __hmul2(u2, RHO2);
            __half2 P  = h2ex2(pu);
            __half2 Pi = h2ex2(__hneg2(pu));
            h2a[5] = __hadd2(h2a[5], w5);
            __half2 rr = w5;
            #pragma unroll
            for (int m = 0; m < 5; m++) {               // bins 4..0 (intermediates = true weights <= 2)
                rr = __hmul2(__hmul2(rr, Pi), RS2[m]);
                h2a[4 - m] = __hadd2(h2a[4 - m], rr);
            }
            rr = w5;
            #pragma unroll
            for (int m = 0; m < 5; m++) {               // bins 6..10
                rr = __hmul2(__hmul2(rr, P), RS2[m]);
                h2a[6 + m] = __hadd2(h2a[6 + m], rr);
            }
        }
        // flush chunk (8 elements) to f32 accumulators
        #pragma unroll
        for (int k = 0; k < NB; k++) {
            float2 t = __half22float2(h2a[k]);
            histf[k] += t.x + t.y;
        }
    }

    // reduce hist, write signature
    #pragma unroll
    for (int k = 0; k < NB; k++)
        #pragma unroll
        for (int o = 16; o; o >>= 1)
            histf[k] += __shfl_xor_sync(0xffffffffu, histf[k], o);
    if (lane == 0) {
        #pragma unroll
        for (int k = 0; k < NB; k++) red[8 + wid * NB + k] = histf[k];
    }
    __syncthreads();

    if (tid < KB) {
        float h = 0.f;
        if (tid < NB) {
            #pragma unroll
            for (int w = 0; w < 8; w++) h += red[8 + w * NB + tid];
        }
        float tot = h;
        #pragma unroll
        for (int o = 8; o; o >>= 1) tot += __shfl_xor_sync(0x0000ffffu, tot, o);
        g_sig[bx * KB + tid] = h / (tot + 1e-8f);
    }
    __syncthreads();

    // ================== NT-Xent row bx ==================
    {
        float* invn = sq;
        const float* zp = (tid < G) ? (z1 + tid * DF) : (z2 + (tid - G) * DF);
        const float4* zp4 = (const float4*)zp;
        float s = 0.f;
        #pragma unroll 8
        for (int k = 0; k < 32; k++) {
            float4 a = zp4[k];
            s = fmaf(a.x, a.x, fmaf(a.y, a.y, fmaf(a.z, a.z, fmaf(a.w, a.w, s))));
        }
        invn[tid] = 1.f / (sqrtf(s) + 1e-8f);

        const float* zrp = (bx < G) ? (z1 + bx * DF) : (z2 + (bx - G) * DF);
        if (tid < 32) ((float4*)zr)[tid] = ((const float4*)zrp)[tid];
        __syncthreads();

        float dot = 0.f;
        const float4* zr4 = (const float4*)zr;
        #pragma unroll 8
        for (int k = 0; k < 32; k++) {
            float4 a = zp4[k], b2 = zr4[k];
            dot = fmaf(a.x, b2.x, fmaf(a.y, b2.y, fmaf(a.z, b2.z, fmaf(a.w, b2.w, dot))));
        }
        float sim = dot * invn[bx] * invn[tid] * 2.0f;
        const int lbl = bx ^ G;
        if (tid == lbl) red[120] = sim;

        float e = (tid == bx) ? 0.f : expf(sim);
        #pragma unroll
        for (int o = 16; o; o >>= 1) e += __shfl_xor_sync(0xffffffffu, e, o);
        __syncthreads();
        if (lane == 0) red[wid] = e;
        __syncthreads();
        if (tid == 0) {
            float S = 0.f;
            #pragma unroll
            for (int w = 0; w < 8; w++) S += red[w];
            g_rowloss[bx] = logf(S) - red[120];
        }
    }

    // ================== last CTA: final reduction ==================
    __shared__ unsigned amLast;
    __syncthreads();
    if (tid == 0) {
        __threadfence();
        unsigned vv = atomicInc(&g_ctr, 255);
        amLast = (vv == 255) ? 1u : 0u;
    }
    __syncthreads();

    if (amLast) {
        __threadfence();
        float a = 0.f;
        for (int idx = tid; idx < G * KB; idx += 256) {
            float d = g_sig[idx] - g_sig[G * KB + idx];
            a += d * d;
        }
        a *= (1.f / 2048.f);
        a += g_rowloss[tid] * (1.f / 256.f);
        #pragma unroll
        for (int o = 16; o; o >>= 1) a += __shfl_xor_sync(0xffffffffu, a, o);
        if (lane == 0) red[64 + wid] = a;
        __syncthreads();
        if (tid == 0) {
            float t = 0.f;
            #pragma unroll
            for (int w = 0; w < 8; w++) t += red[64 + w];
            out[0] = 0.1f * t;
        }
    }
}

extern "C" void kernel_launch(void* const* d_in, const int* in_sizes, int n_in,
                              void* d_out, int out_size)
{
    const float* H1 = (const float*)d_in[0];
    const float* H2 = (const float*)d_in[2];
    const float* z1 = (const float*)d_in[4];
    const float* z2 = (const float*)d_in[5];
    float* out = (float*)d_out;

    cudaFuncSetAttribute(uts_kernel, cudaFuncAttributeMaxDynamicSharedMemorySize, SMEM_A);
    uts_kernel<<<256, 256, SMEM_A>>>(H1, H2, z1, z2, out);
}